// round 12
// baseline (speedup 1.0000x reference)
#include <cuda_runtime.h>
#include <cuda_bf16.h>

// Soft histogram via sub-bin counting + kernel-table convolution, v3.
// out[b,k] = (1/N) sum_n g(c_n - k),  c = x*256,  g(v) = sig(2.5v) - sig(2.5(v-1))
//
// v3 vs v2 (18.9us): replace shared float atomics (spread-ATOMS floor ~2cyc/lane,
// ~14us/SM) with per-warp private u16 histograms updated via
// __match_any_sync dedup + leader LDS/STS (crossbar throughput). Merge the 8
// warp copies once (I2F per bin, not per conv tap), then the same 192-tap
// conflict-free convolution. Also 4x-unrolled loads (MLP 4/warp).

#define THREADS   256
#define SUBBINS   4096
#define HSLOTS    4097            // +1 slot for s == 4096
#define WSTRIDE   4104            // u16 elements per warp hist (8-aligned)
#define NW        8               // warps per block
#define TBL       192             // taps: v = (jj - 88)/16
#define KBINS     256
#define P         18              // blocks per batch -> 144 blocks = 1/SM

// dynamic smem layout:
//   u16  whist[NW*WSTRIDE]                  (65664 B)
//   float T[TBL]                            (  768 B)
//   float merged[HSLOTS]                    (16388 B)
#define OFF_T       (NW * WSTRIDE * 2)
#define OFF_MERGED  (OFF_T + TBL * 4)
#define SMEM_BYTES  (OFF_MERGED + HSLOTS * 4)

__global__ void zero_kernel(float* out, int n) {
    int i = blockIdx.x * blockDim.x + threadIdx.x;
    if (i < n) out[i] = 0.0f;
}

__device__ __forceinline__ void bump(unsigned short* myh, int lane, float f) {
    int s = min(max(__float2int_rn(f * 4096.0f), 0), 4096);
    int a = (s < 4096) ? (((s & 15) << 8) | (s >> 4)) : 4096;
    unsigned m = __match_any_sync(0xffffffffu, a);
    int cnt = __popc(m);
    if (lane == (__ffs(m) - 1)) {
        myh[a] = (unsigned short)(myh[a] + cnt);
    }
}

__global__ __launch_bounds__(THREADS)
void hist_kernel(const float* __restrict__ x, float* __restrict__ out,
                 int N4, float inv_n)
{
    extern __shared__ unsigned char smem_raw[];
    unsigned short* whist  = (unsigned short*)smem_raw;
    float*          T      = (float*)(smem_raw + OFF_T);
    float*          merged = (float*)(smem_raw + OFF_MERGED);

    const int tid   = threadIdx.x;
    const int lane  = tid & 31;
    const int wid   = tid >> 5;
    const int batch = blockIdx.y;
    unsigned short* myh = whist + wid * WSTRIDE;

    // init: zero per-warp histograms (uint4 stores), build g table
    {
        uint4* z = (uint4*)whist;                 // NW*WSTRIDE/8 = 4104 uint4
        const uint4 zero = make_uint4(0, 0, 0, 0);
        for (int i = tid; i < NW * WSTRIDE / 8; i += THREADS) z[i] = zero;
    }
    if (tid < TBL) {
        float v  = (float)(tid - 88) * (1.0f / 16.0f);
        float aa = 2.5f * v;
        float bb = aa - 2.5f;
        float sa = 1.0f / (1.0f + __expf(-aa));
        float sb = 1.0f / (1.0f + __expf(-bb));
        T[tid] = sa - sb;
    }
    __syncthreads();

    // phase 1: per-warp u16 histogram, match_any dedup, 4x-unrolled loads.
    // Guard branches are warp-uniform (lane i's are 32 consecutive, 32-aligned;
    // N4 and strides are multiples of 32), so full-mask match_any is valid.
    const float4* xb = reinterpret_cast<const float4*>(x) + (size_t)batch * (size_t)N4;
    const int STRIDE = P * THREADS;
    for (int i = blockIdx.x * THREADS + tid; i < N4; i += 4 * STRIDE) {
        const int i1 = i + STRIDE, i2 = i + 2 * STRIDE, i3 = i + 3 * STRIDE;
        const bool b1 = i1 < N4, b2 = i2 < N4, b3 = i3 < N4;
        float4 v0, v1, v2, v3;
        v0 = xb[i];
        if (b1) v1 = xb[i1];
        if (b2) v2 = xb[i2];
        if (b3) v3 = xb[i3];

        bump(myh, lane, v0.x); bump(myh, lane, v0.y);
        bump(myh, lane, v0.z); bump(myh, lane, v0.w);
        if (b1) { bump(myh, lane, v1.x); bump(myh, lane, v1.y);
                  bump(myh, lane, v1.z); bump(myh, lane, v1.w); }
        if (b2) { bump(myh, lane, v2.x); bump(myh, lane, v2.y);
                  bump(myh, lane, v2.z); bump(myh, lane, v2.w); }
        if (b3) { bump(myh, lane, v3.x); bump(myh, lane, v3.y);
                  bump(myh, lane, v3.z); bump(myh, lane, v3.w); }
    }
    __syncthreads();

    // merge: sum 8 warp copies per bin, convert to float once.
    // Consecutive tid -> consecutive u16 addresses: conflict-free.
    for (int d = tid; d < HSLOTS; d += THREADS) {
        int sum = 0;
        #pragma unroll
        for (int w = 0; w < NW; w++) sum += (int)whist[w * WSTRIDE + d];
        merged[d] = (float)sum;
    }
    __syncthreads();

    // phase 2: 192-tap convolution, conflict-free (permuted layout).
    // thread k sums over s = 16k - 88 + jj.
    const int k = tid;  // THREADS == KBINS
    float acc = 0.0f;
    if (k >= 6 && k <= 249) {
        const int b = k - 6;
        #pragma unroll
        for (int jj = 0; jj < TBL; jj++) {
            const int m = jj + 8;
            acc += T[jj] * merged[((m & 15) << 8) + (m >> 4) + b];
        }
    } else {
        const int s0 = 16 * k - 88;
        for (int jj = 0; jj < TBL; jj++) {
            int s = s0 + jj;
            if (s >= 0 && s <= 4096) {
                int a = (s < 4096) ? (((s & 15) << 8) | (s >> 4)) : 4096;
                acc += T[jj] * merged[a];
            }
        }
    }
    atomicAdd(&out[batch * KBINS + k], acc * inv_n);
}

extern "C" void kernel_launch(void* const* d_in, const int* in_sizes, int n_in,
                              void* d_out, int out_size) {
    const float* x = (const float*)d_in[0];
    float* out = (float*)d_out;

    int B  = out_size / KBINS;        // 8
    int N  = in_sizes[0] / B;         // 262144
    int N4 = N / 4;

    cudaFuncSetAttribute(hist_kernel,
                         cudaFuncAttributeMaxDynamicSharedMemorySize, SMEM_BYTES);

    zero_kernel<<<(out_size + THREADS - 1) / THREADS, THREADS>>>(out, out_size);

    dim3 grid(P, B);
    hist_kernel<<<grid, THREADS, SMEM_BYTES>>>(x, out, N4, 1.0f / (float)N);
}